// round 5
// baseline (speedup 1.0000x reference)
#include <cuda_runtime.h>
#include <cuda_bf16.h>
#include <math.h>

// ---------------- problem constants ----------------
#define L_IN   20197
#define BATCH  2
#define M_TOT  (BATCH * L_IN)      // 40394
#define DMODEL 256
#define DFFN   1024
#define NHEADS 8
#define HDIM   32
#define NLVL   4
#define NPTS   4

__constant__ int c_Hs[NLVL]    = {100, 50, 25, 13};
__constant__ int c_Ws[NLVL]    = {152, 76, 38, 19};
__constant__ int c_start[NLVL] = {0, 15200, 19000, 19950};

// ---------------- scratch (alloc-free: __device__ globals) ----------------
__device__ float g_query[M_TOT * DMODEL];
__device__ float g_value[M_TOT * DMODEL];
__device__ float g_off  [M_TOT * DMODEL];          // (row, h,l,p,xy) = 256
__device__ float g_attn [M_TOT * NHEADS * 16];     // logits
__device__ float g_samp [M_TOT * DMODEL];
__device__ float g_src2 [M_TOT * DMODEL];
__device__ float g_x    [M_TOT * DMODEL];
__device__ float g_ffn  [M_TOT * DFFN];
__device__ float g_y    [M_TOT * DMODEL];

// ---------------- elementwise add ----------------
__global__ void add2_kernel(const float* __restrict__ a, const float* __restrict__ b,
                            float* __restrict__ o, int n) {
    int i = blockIdx.x * blockDim.x + threadIdx.x;
    if (i < n) o[i] = a[i] + b[i];
}

// ---------------- SGEMM: C[M,N] = A[M,K] @ B[K,N] + bias (opt relu) ----------------
// BM=128 BN=128 BK=16, 256 threads, 8x8 per thread, double-buffered smem.
// N, K multiples of 128/16; M guarded.
#define BM 128
#define BN 128
#define BKK 16
#define TM 8
#define TN 8

template<bool RELU>
__global__ __launch_bounds__(256)
void sgemm_bias(const float* __restrict__ A, const float* __restrict__ B,
                const float* __restrict__ bias, float* __restrict__ C,
                int M, int N, int K) {
    __shared__ float As[2][BKK][BM];
    __shared__ float Bs[2][BKK][BN];

    const int tid = threadIdx.x;
    const int m0 = blockIdx.y * BM;
    const int n0 = blockIdx.x * BN;

    const int rowA = tid >> 2;          // 0..63
    const int colA = (tid & 3) << 2;    // 0,4,8,12
    const int rowB = tid >> 5;          // 0..7
    const int colB = (tid & 31) << 2;   // 0..124

    const int tr = (tid >> 4) * TM;
    const int tc = (tid & 15) * TN;

    float acc[TM][TN];
#pragma unroll
    for (int i = 0; i < TM; i++)
#pragma unroll
        for (int j = 0; j < TN; j++) acc[i][j] = 0.f;

    // tile loader: global (k0) -> smem buffer bf
    auto load_tile = [&](int bf, int k0) {
#pragma unroll
        for (int r = 0; r < 2; r++) {
            int m = m0 + rowA + r * 64;
            float4 v = make_float4(0.f, 0.f, 0.f, 0.f);
            if (m < M) v = *(const float4*)(A + (size_t)m * K + k0 + colA);
            As[bf][colA + 0][rowA + r * 64] = v.x;
            As[bf][colA + 1][rowA + r * 64] = v.y;
            As[bf][colA + 2][rowA + r * 64] = v.z;
            As[bf][colA + 3][rowA + r * 64] = v.w;
        }
#pragma unroll
        for (int r = 0; r < 2; r++) {
            int k = rowB + r * 8;
            *(float4*)(&Bs[bf][k][colB]) = *(const float4*)(B + (size_t)(k0 + k) * N + n0 + colB);
        }
    };

    // prologue: stage tile 0
    load_tile(0, 0);
    __syncthreads();

    int cur = 0;
    for (int k0 = 0; k0 < K; k0 += BKK) {
        const int nxt = cur ^ 1;
        if (k0 + BKK < K) load_tile(nxt, k0 + BKK);   // writes other buffer

#pragma unroll
        for (int kk = 0; kk < BKK; kk++) {
            float rm[TM], rn[TN];
#pragma unroll
            for (int i = 0; i < TM; i++) rm[i] = As[cur][kk][tr + i];
#pragma unroll
            for (int j = 0; j < TN; j++) rn[j] = Bs[cur][kk][tc + j];
#pragma unroll
            for (int i = 0; i < TM; i++)
#pragma unroll
                for (int j = 0; j < TN; j++) acc[i][j] += rm[i] * rn[j];
        }
        __syncthreads();   // next tile visible; this buffer safe to overwrite next iter
        cur = nxt;
    }

#pragma unroll
    for (int i = 0; i < TM; i++) {
        int m = m0 + tr + i;
        if (m >= M) break;
#pragma unroll
        for (int j = 0; j < TN; j += 4) {
            float4 bv = *(const float4*)(bias + n0 + tc + j);
            float4 o;
            o.x = acc[i][j + 0] + bv.x;
            o.y = acc[i][j + 1] + bv.y;
            o.z = acc[i][j + 2] + bv.z;
            o.w = acc[i][j + 3] + bv.w;
            if (RELU) {
                o.x = fmaxf(o.x, 0.f); o.y = fmaxf(o.y, 0.f);
                o.z = fmaxf(o.z, 0.f); o.w = fmaxf(o.w, 0.f);
            }
            *(float4*)(C + (size_t)m * N + n0 + tc + j) = o;
        }
    }
}

// ---------------- deformable sampling ----------------
// one block per query row, one warp per head, lane = head-dim channel.
__global__ __launch_bounds__(256)
void sample_kernel(const float* __restrict__ ref) {
    const int row  = blockIdx.x;
    const int h    = threadIdx.x >> 5;
    const int lane = threadIdx.x & 31;
    const int b    = row / L_IN;

    // softmax over 16 logits for this head (lane-redundant broadcast loads)
    const float* attnp = g_attn + (size_t)row * (NHEADS * 16) + h * 16;
    float w[16];
    float mx = -1e30f;
#pragma unroll
    for (int j = 0; j < 16; j++) { w[j] = __ldg(attnp + j); mx = fmaxf(mx, w[j]); }
    float s = 0.f;
#pragma unroll
    for (int j = 0; j < 16; j++) { w[j] = __expf(w[j] - mx); s += w[j]; }
    const float inv = 1.f / s;

    const float* offp = g_off + (size_t)row * DMODEL + h * (NLVL * NPTS * 2);
    const float* refp = ref + (size_t)row * (NLVL * 2);
    const float* vbase = g_value + (size_t)b * L_IN * DMODEL + h * HDIM + lane;

    float acc = 0.f;
#pragma unroll
    for (int l = 0; l < NLVL; l++) {
        const float rx = __ldg(refp + 2 * l + 0);
        const float ry = __ldg(refp + 2 * l + 1);
        const int W  = c_Ws[l];
        const int Hh = c_Hs[l];
        const int st = c_start[l];
        const float fW = (float)W, fH = (float)Hh;
#pragma unroll
        for (int p = 0; p < NPTS; p++) {
            const float ox = __ldg(offp + (l * NPTS + p) * 2 + 0);
            const float oy = __ldg(offp + (l * NPTS + p) * 2 + 1);
            const float x = (rx + ox / fW) * fW - 0.5f;
            const float y = (ry + oy / fH) * fH - 0.5f;
            const float x0f = floorf(x), y0f = floorf(y);
            const int x0 = (int)x0f, y0 = (int)y0f;
            const float fx = x - x0f, fy = y - y0f;
            const float aw = w[l * NPTS + p] * inv;

            const float w00 = aw * (1.f - fx) * (1.f - fy);
            const float w10 = aw * fx * (1.f - fy);
            const float w01 = aw * (1.f - fx) * fy;
            const float w11 = aw * fx * fy;

            const bool vx0 = (x0 >= 0) & (x0 < W);
            const bool vx1 = (x0 + 1 >= 0) & (x0 + 1 < W);
            const bool vy0 = (y0 >= 0) & (y0 < Hh);
            const bool vy1 = (y0 + 1 >= 0) & (y0 + 1 < Hh);

            if (vx0 & vy0) acc = fmaf(w00, __ldg(vbase + (size_t)(st + y0 * W + x0) * DMODEL), acc);
            if (vx1 & vy0) acc = fmaf(w10, __ldg(vbase + (size_t)(st + y0 * W + x0 + 1) * DMODEL), acc);
            if (vx0 & vy1) acc = fmaf(w01, __ldg(vbase + (size_t)(st + (y0 + 1) * W + x0) * DMODEL), acc);
            if (vx1 & vy1) acc = fmaf(w11, __ldg(vbase + (size_t)(st + (y0 + 1) * W + x0 + 1) * DMODEL), acc);
        }
    }
    g_samp[(size_t)row * DMODEL + h * HDIM + lane] = acc;
}

// ---------------- residual add + LayerNorm (dim 256) ----------------
__global__ __launch_bounds__(256)
void add_ln_kernel(const float* __restrict__ a, const float* __restrict__ b,
                   const float* __restrict__ g, const float* __restrict__ beta,
                   float* __restrict__ out) {
    const int row = blockIdx.x;
    const int t = threadIdx.x;
    const int lane = t & 31, warp = t >> 5;
    __shared__ float red[8];

    const float v = a[(size_t)row * DMODEL + t] + b[(size_t)row * DMODEL + t];

    // mean
    float s = v;
#pragma unroll
    for (int o = 16; o > 0; o >>= 1) s += __shfl_xor_sync(0xffffffffu, s, o);
    if (lane == 0) red[warp] = s;
    __syncthreads();
    if (warp == 0) {
        float x = (lane < 8) ? red[lane] : 0.f;
#pragma unroll
        for (int o = 4; o > 0; o >>= 1) x += __shfl_xor_sync(0xffffffffu, x, o);
        if (lane == 0) red[0] = x;
    }
    __syncthreads();
    const float mean = red[0] * (1.f / DMODEL);
    __syncthreads();

    // variance
    const float d = v - mean;
    float s2 = d * d;
#pragma unroll
    for (int o = 16; o > 0; o >>= 1) s2 += __shfl_xor_sync(0xffffffffu, s2, o);
    if (lane == 0) red[warp] = s2;
    __syncthreads();
    if (warp == 0) {
        float x = (lane < 8) ? red[lane] : 0.f;
#pragma unroll
        for (int o = 4; o > 0; o >>= 1) x += __shfl_xor_sync(0xffffffffu, x, o);
        if (lane == 0) red[0] = x;
    }
    __syncthreads();
    const float var = red[0] * (1.f / DMODEL);

    out[(size_t)row * DMODEL + t] = d * rsqrtf(var + 1e-5f) * g[t] + beta[t];
}

// ---------------- launch ----------------
extern "C" void kernel_launch(void* const* d_in, const int* in_sizes, int n_in,
                              void* d_out, int out_size) {
    const float* src    = (const float*)d_in[0];
    const float* pos    = (const float*)d_in[1];
    const float* ref    = (const float*)d_in[2];
    // d_in[3] spatial_shapes, d_in[4] level_start_index: compile-time constants
    const float* W_off  = (const float*)d_in[5];
    const float* b_off  = (const float*)d_in[6];
    const float* W_attn = (const float*)d_in[7];
    const float* b_attn = (const float*)d_in[8];
    const float* W_val  = (const float*)d_in[9];
    const float* b_val  = (const float*)d_in[10];
    const float* W_out  = (const float*)d_in[11];
    const float* b_out  = (const float*)d_in[12];
    const float* W1     = (const float*)d_in[13];
    const float* b1     = (const float*)d_in[14];
    const float* W2     = (const float*)d_in[15];
    const float* b2     = (const float*)d_in[16];
    const float* g1     = (const float*)d_in[17];
    const float* be1    = (const float*)d_in[18];
    const float* g2     = (const float*)d_in[19];
    const float* be2    = (const float*)d_in[20];
    float* out = (float*)d_out;

    float *q, *val, *off, *attn, *samp, *src2, *x, *ffn, *y;
    cudaGetSymbolAddress((void**)&q,    g_query);
    cudaGetSymbolAddress((void**)&val,  g_value);
    cudaGetSymbolAddress((void**)&off,  g_off);
    cudaGetSymbolAddress((void**)&attn, g_attn);
    cudaGetSymbolAddress((void**)&samp, g_samp);
    cudaGetSymbolAddress((void**)&src2, g_src2);
    cudaGetSymbolAddress((void**)&x,    g_x);
    cudaGetSymbolAddress((void**)&ffn,  g_ffn);
    cudaGetSymbolAddress((void**)&y,    g_y);

    const int M = M_TOT;
    const int mb = (M + BM - 1) / BM;   // 316
    dim3 gN256(DMODEL / BN, mb);
    dim3 gN128(1, mb);
    dim3 gN1024(DFFN / BN, mb);

    // query = src + pos
    add2_kernel<<<(M * DMODEL + 255) / 256, 256>>>(src, pos, q, M * DMODEL);

    // value = src @ W_val + b_val
    sgemm_bias<false><<<gN256, 256>>>(src, W_val, b_val, val, M, DMODEL, DMODEL);
    // offsets = query @ W_off + b_off
    sgemm_bias<false><<<gN256, 256>>>(q, W_off, b_off, off, M, DMODEL, DMODEL);
    // attn logits = query @ W_attn + b_attn
    sgemm_bias<false><<<gN128, 256>>>(q, W_attn, b_attn, attn, M, NHEADS * 16, DMODEL);

    // deformable sampling (softmax fused)
    sample_kernel<<<M, 256>>>(ref);

    // src2 = samp @ W_out + b_out
    sgemm_bias<false><<<gN256, 256>>>(samp, W_out, b_out, src2, M, DMODEL, DMODEL);

    // x = LN(src + src2)
    add_ln_kernel<<<M, 256>>>(src, src2, g1, be1, x);

    // ffn hidden = relu(x @ W1 + b1)
    sgemm_bias<true><<<gN1024, 256>>>(x, W1, b1, ffn, M, DFFN, DMODEL);
    // y = ffn @ W2 + b2
    sgemm_bias<false><<<gN256, 256>>>(ffn, W2, b2, y, M, DMODEL, DFFN);

    // out = LN(x + y)
    add_ln_kernel<<<M, 256>>>(x, y, g2, be2, out);
}

// round 8
// speedup vs baseline: 1.2532x; 1.2532x over previous
#include <cuda_runtime.h>
#include <cuda_bf16.h>
#include <math.h>
#include <stdint.h>

// ---------------- problem constants ----------------
#define L_IN   20197
#define BATCH  2
#define M_TOT  (BATCH * L_IN)      // 40394
#define DMODEL 256
#define DFFN   1024
#define NHEADS 8
#define HDIM   32
#define NLVL   4
#define NPTS   4

__constant__ int c_Hs[NLVL]    = {100, 50, 25, 13};
__constant__ int c_Ws[NLVL]    = {152, 76, 38, 19};
__constant__ int c_start[NLVL] = {0, 15200, 19000, 19950};

// ---------------- scratch (alloc-free: __device__ globals) ----------------
__device__ float g_value[M_TOT * DMODEL];
__device__ float g_off  [M_TOT * DMODEL];
__device__ float g_attn [M_TOT * NHEADS * 16];
__device__ float g_src2 [M_TOT * DMODEL];
__device__ float g_x    [M_TOT * DMODEL];
__device__ float g_y    [M_TOT * DMODEL];
__device__ __nv_bfloat16 g_src_h[M_TOT * DMODEL];
__device__ __nv_bfloat16 g_src_l[M_TOT * DMODEL];
__device__ __nv_bfloat16 g_q_h  [M_TOT * DMODEL];
__device__ __nv_bfloat16 g_q_l  [M_TOT * DMODEL];
__device__ __nv_bfloat16 g_sm_h [M_TOT * DMODEL];
__device__ __nv_bfloat16 g_sm_l [M_TOT * DMODEL];
__device__ __nv_bfloat16 g_x_h  [M_TOT * DMODEL];
__device__ __nv_bfloat16 g_x_l  [M_TOT * DMODEL];
__device__ __nv_bfloat16 g_f_h  [M_TOT * DFFN];
__device__ __nv_bfloat16 g_f_l  [M_TOT * DFFN];
__device__ __nv_bfloat16 g_wv_h[DMODEL * DMODEL];
__device__ __nv_bfloat16 g_wv_l[DMODEL * DMODEL];
__device__ __nv_bfloat16 g_wo_h[DMODEL * DMODEL];
__device__ __nv_bfloat16 g_wo_l[DMODEL * DMODEL];
__device__ __nv_bfloat16 g_wa_h[(NHEADS * 16) * DMODEL];
__device__ __nv_bfloat16 g_wa_l[(NHEADS * 16) * DMODEL];
__device__ __nv_bfloat16 g_wu_h[DMODEL * DMODEL];
__device__ __nv_bfloat16 g_wu_l[DMODEL * DMODEL];
__device__ __nv_bfloat16 g_w1_h[DFFN * DMODEL];
__device__ __nv_bfloat16 g_w1_l[DFFN * DMODEL];
__device__ __nv_bfloat16 g_w2_h[DMODEL * DFFN];
__device__ __nv_bfloat16 g_w2_l[DMODEL * DFFN];

// ---------------- warp MMA helpers (sm_80+ portable PTX; HMMA pipe) ----------------
__device__ __forceinline__ uint32_t smem_u32(const void* p) {
    uint32_t a;
    asm("{ .reg .u64 t; cvta.to.shared.u64 t, %1; cvt.u32.u64 %0, t; }" : "=r"(a) : "l"(p));
    return a;
}
#define LDSM_X4(r0, r1, r2, r3, addr) \
    asm volatile("ldmatrix.sync.aligned.m8n8.x4.shared.b16 {%0,%1,%2,%3}, [%4];" \
                 : "=r"(r0), "=r"(r1), "=r"(r2), "=r"(r3) : "r"(addr))

__device__ __forceinline__ void mma16816(float* c, const uint32_t* a, const uint32_t* b) {
    asm volatile(
        "mma.sync.aligned.m16n8k16.row.col.f32.bf16.bf16.f32 "
        "{%0,%1,%2,%3}, {%4,%5,%6,%7}, {%8,%9}, {%0,%1,%2,%3};"
        : "+f"(c[0]), "+f"(c[1]), "+f"(c[2]), "+f"(c[3])
        : "r"(a[0]), "r"(a[1]), "r"(a[2]), "r"(a[3]), "r"(b[0]), "r"(b[1]));
}

// ---------------- bf16 mma GEMM ----------------
// C[M,N] = A @ W + bias; A = Ahi+Alo (bf16 split [M,K]); W^T = Bhi+Blo ([N,K]).
// Logical K' = 3K: segments hi*hi, hi*lo, lo*hi.
// Tile 128x128, 8 warps (4m x 2n), 32x64 per warp, BK=32, double-buffered smem.
#define LDP 40   // padded row length (bf16): 80 bytes -> conflict-free ldmatrix

template<bool RELU, bool WF32, bool WSPLIT>
__global__ __launch_bounds__(256)
void mma_gemm(const __nv_bfloat16* __restrict__ Ahi, const __nv_bfloat16* __restrict__ Alo,
              const __nv_bfloat16* __restrict__ Bhi, const __nv_bfloat16* __restrict__ Blo,
              const float* __restrict__ bias, float* __restrict__ Cf,
              __nv_bfloat16* __restrict__ Chi, __nv_bfloat16* __restrict__ Clo,
              int M, int N, int K) {
    __shared__ __nv_bfloat16 As[2][128][LDP];
    __shared__ __nv_bfloat16 Bs[2][128][LDP];

    const int tid = threadIdx.x;
    const int wid = tid >> 5, lane = tid & 31;
    const int warp_m = wid >> 1;          // 0..3 -> m offset *32
    const int warp_n = wid & 1;           // 0..1 -> n offset *64
    const int m0 = blockIdx.y * 128;
    const int n0 = blockIdx.x * 128;

    float acc[2][8][4];
#pragma unroll
    for (int mt = 0; mt < 2; mt++)
#pragma unroll
        for (int nt = 0; nt < 8; nt++)
#pragma unroll
            for (int e = 0; e < 4; e++) acc[mt][nt][e] = 0.f;

    const int K32 = K >> 5;
    const int nch = 3 * K32;

    auto srcA = [&](int i) { return (i < 2 * K32) ? Ahi : Alo; };
    auto srcB = [&](int i) { return (i / K32 == 1) ? Blo : Bhi; };
    auto k0of = [&](int i) { return (i % K32) * 32; };

    auto load_tile = [&](int buf, int i) {
        const __nv_bfloat16* A = srcA(i);
        const __nv_bfloat16* B = srcB(i);
        const int k0 = k0of(i);
#pragma unroll
        for (int rep = 0; rep < 2; rep++) {
            int u = rep * 256 + tid;
            int row = u >> 2, j = u & 3;
            uint4 v = make_uint4(0u, 0u, 0u, 0u);
            int gr = m0 + row;
            if (gr < M) v = *(const uint4*)(A + (size_t)gr * K + k0 + j * 8);
            *(uint4*)(&As[buf][row][j * 8]) = v;
        }
#pragma unroll
        for (int rep = 0; rep < 2; rep++) {
            int u = rep * 256 + tid;
            int row = u >> 2, j = u & 3;
            uint4 v = *(const uint4*)(B + (size_t)(n0 + row) * K + k0 + j * 8);
            *(uint4*)(&Bs[buf][row][j * 8]) = v;
        }
    };

    load_tile(0, 0);
    __syncthreads();

    // per-warp ldmatrix byte offsets (within a buffer), excluding k-step part
    const uint32_t sA = smem_u32(&As[0][0][0]);
    const uint32_t sB = smem_u32(&Bs[0][0][0]);
    const uint32_t aRow = (uint32_t)(warp_m * 32 + (lane & 15));           // + mt*16
    const uint32_t aCol = (uint32_t)((lane >> 4) * 8);                     // + ks*16
    const uint32_t bRow = (uint32_t)(warp_n * 64 + ((lane >> 4) << 3) + (lane & 7));  // + np*16
    const uint32_t bCol = (uint32_t)(((lane >> 3) & 1) * 8);               // + ks*16

    for (int i = 0; i < nch; i++) {
        const int cur = i & 1;
        if (i + 1 < nch) load_tile(cur ^ 1, i + 1);

        const uint32_t baseA = sA + (uint32_t)cur * 128 * LDP * 2;
        const uint32_t baseB = sB + (uint32_t)cur * 128 * LDP * 2;
#pragma unroll
        for (int ks = 0; ks < 2; ks++) {
            uint32_t af[2][4];
#pragma unroll
            for (int mt = 0; mt < 2; mt++) {
                uint32_t addr = baseA + ((aRow + mt * 16) * LDP + aCol + ks * 16) * 2;
                LDSM_X4(af[mt][0], af[mt][1], af[mt][2], af[mt][3], addr);
            }
            uint32_t bfr[8][2];
#pragma unroll
            for (int np = 0; np < 4; np++) {
                uint32_t addr = baseB + ((bRow + np * 16) * LDP + bCol + ks * 16) * 2;
                uint32_t r0, r1, r2, r3;
                LDSM_X4(r0, r1, r2, r3, addr);
                bfr[np * 2 + 0][0] = r0; bfr[np * 2 + 0][1] = r1;
                bfr[np * 2 + 1][0] = r2; bfr[np * 2 + 1][1] = r3;
            }
#pragma unroll
            for (int mt = 0; mt < 2; mt++)
#pragma unroll
                for (int nt = 0; nt < 8; nt++)
                    mma16816(acc[mt][nt], af[mt], bfr[nt]);
        }
        __syncthreads();
    }

    // epilogue from fragments: thread covers rows {g, g+8} per mtile, cols q*2,q*2+1
    const int g = lane >> 2, q = lane & 3;
#pragma unroll
    for (int mt = 0; mt < 2; mt++) {
#pragma unroll
        for (int nt = 0; nt < 8; nt++) {
            const int gn = n0 + warp_n * 64 + nt * 8 + q * 2;
            const float b0 = __ldg(bias + gn), b1 = __ldg(bias + gn + 1);
#pragma unroll
            for (int half = 0; half < 2; half++) {
                const int gm = m0 + warp_m * 32 + mt * 16 + g + half * 8;
                if (gm < M) {
                    float v0 = acc[mt][nt][half * 2 + 0] + b0;
                    float v1 = acc[mt][nt][half * 2 + 1] + b1;
                    if (RELU) { v0 = fmaxf(v0, 0.f); v1 = fmaxf(v1, 0.f); }
                    const size_t base = (size_t)gm * N + gn;
                    if (WF32) {
                        Cf[base + 0] = v0;
                        Cf[base + 1] = v1;
                    }
                    if (WSPLIT) {
                        __nv_bfloat16 h0 = __float2bfloat16(v0);
                        __nv_bfloat16 h1 = __float2bfloat16(v1);
                        Chi[base + 0] = h0; Chi[base + 1] = h1;
                        Clo[base + 0] = __float2bfloat16(v0 - __bfloat162float(h0));
                        Clo[base + 1] = __float2bfloat16(v1 - __bfloat162float(h1));
                    }
                }
            }
        }
    }
}

// ---------------- small prep kernels ----------------
__global__ void split_f32(const float* __restrict__ in,
                          __nv_bfloat16* __restrict__ h, __nv_bfloat16* __restrict__ l, int n) {
    int i = blockIdx.x * blockDim.x + threadIdx.x;
    if (i < n) {
        float v = in[i];
        __nv_bfloat16 hi = __float2bfloat16(v);
        h[i] = hi;
        l[i] = __float2bfloat16(v - __bfloat162float(hi));
    }
}

__global__ void add2_split(const float* __restrict__ a, const float* __restrict__ b,
                           __nv_bfloat16* __restrict__ h, __nv_bfloat16* __restrict__ l, int n) {
    int i = blockIdx.x * blockDim.x + threadIdx.x;
    if (i < n) {
        float v = a[i] + b[i];
        __nv_bfloat16 hi = __float2bfloat16(v);
        h[i] = hi;
        l[i] = __float2bfloat16(v - __bfloat162float(hi));
    }
}

// W[K,N] f32 -> Whi/Wlo [N,K] bf16
__global__ void transpose_split(const float* __restrict__ in,
                                __nv_bfloat16* __restrict__ h, __nv_bfloat16* __restrict__ l,
                                int K, int N) {
    __shared__ float t[32][33];
    int n0 = blockIdx.x * 32, k0 = blockIdx.y * 32;
    int x = threadIdx.x, y = threadIdx.y;   // 32 x 8
#pragma unroll
    for (int r = 0; r < 32; r += 8) {
        int k = k0 + y + r, n = n0 + x;
        t[y + r][x] = (k < K && n < N) ? in[(size_t)k * N + n] : 0.f;
    }
    __syncthreads();
#pragma unroll
    for (int r = 0; r < 32; r += 8) {
        int n = n0 + y + r, k = k0 + x;
        if (n < N && k < K) {
            float v = t[x][y + r];
            __nv_bfloat16 hi = __float2bfloat16(v);
            h[(size_t)n * K + k] = hi;
            l[(size_t)n * K + k] = __float2bfloat16(v - __bfloat162float(hi));
        }
    }
}

// ---------------- deformable sampling ----------------
__global__ __launch_bounds__(256)
void sample_kernel(const float* __restrict__ ref) {
    const int row  = blockIdx.x;
    const int h    = threadIdx.x >> 5;
    const int lane = threadIdx.x & 31;
    const int b    = row / L_IN;

    const float* attnp = g_attn + (size_t)row * (NHEADS * 16) + h * 16;
    float w[16];
    float mx = -1e30f;
#pragma unroll
    for (int j = 0; j < 16; j++) { w[j] = __ldg(attnp + j); mx = fmaxf(mx, w[j]); }
    float s = 0.f;
#pragma unroll
    for (int j = 0; j < 16; j++) { w[j] = __expf(w[j] - mx); s += w[j]; }
    const float inv = 1.f / s;

    const float* offp = g_off + (size_t)row * DMODEL + h * (NLVL * NPTS * 2);
    const float* refp = ref + (size_t)row * (NLVL * 2);
    const float* vbase = g_value + (size_t)b * L_IN * DMODEL + h * HDIM + lane;

    float acc = 0.f;
#pragma unroll
    for (int l = 0; l < NLVL; l++) {
        const float rx = __ldg(refp + 2 * l + 0);
        const float ry = __ldg(refp + 2 * l + 1);
        const int W  = c_Ws[l];
        const int Hh = c_Hs[l];
        const int st = c_start[l];
        const float fW = (float)W, fH = (float)Hh;
#pragma unroll
        for (int p = 0; p < NPTS; p++) {
            const float ox = __ldg(offp + (l * NPTS + p) * 2 + 0);
            const float oy = __ldg(offp + (l * NPTS + p) * 2 + 1);
            const float x = (rx + ox / fW) * fW - 0.5f;
            const float y = (ry + oy / fH) * fH - 0.5f;
            const float x0f = floorf(x), y0f = floorf(y);
            const int x0 = (int)x0f, y0 = (int)y0f;
            const float fx = x - x0f, fy = y - y0f;
            const float aw = w[l * NPTS + p] * inv;

            const float w00 = aw * (1.f - fx) * (1.f - fy);
            const float w10 = aw * fx * (1.f - fy);
            const float w01 = aw * (1.f - fx) * fy;
            const float w11 = aw * fx * fy;

            const bool vx0 = (x0 >= 0) & (x0 < W);
            const bool vx1 = (x0 + 1 >= 0) & (x0 + 1 < W);
            const bool vy0 = (y0 >= 0) & (y0 < Hh);
            const bool vy1 = (y0 + 1 >= 0) & (y0 + 1 < Hh);

            if (vx0 & vy0) acc = fmaf(w00, __ldg(vbase + (size_t)(st + y0 * W + x0) * DMODEL), acc);
            if (vx1 & vy0) acc = fmaf(w10, __ldg(vbase + (size_t)(st + y0 * W + x0 + 1) * DMODEL), acc);
            if (vx0 & vy1) acc = fmaf(w01, __ldg(vbase + (size_t)(st + (y0 + 1) * W + x0) * DMODEL), acc);
            if (vx1 & vy1) acc = fmaf(w11, __ldg(vbase + (size_t)(st + (y0 + 1) * W + x0 + 1) * DMODEL), acc);
        }
    }
    size_t oi = (size_t)row * DMODEL + h * HDIM + lane;
    __nv_bfloat16 hi = __float2bfloat16(acc);
    g_sm_h[oi] = hi;
    g_sm_l[oi] = __float2bfloat16(acc - __bfloat162float(hi));
}

// ---------------- residual add + LayerNorm (dim 256), optional bf16-split out ----------------
template<bool WB>
__global__ __launch_bounds__(256)
void add_ln_kernel(const float* __restrict__ a, const float* __restrict__ b,
                   const float* __restrict__ g, const float* __restrict__ beta,
                   float* __restrict__ out,
                   __nv_bfloat16* __restrict__ oh, __nv_bfloat16* __restrict__ ol) {
    const int row = blockIdx.x;
    const int t = threadIdx.x;
    const int lane = t & 31, warp = t >> 5;
    __shared__ float red[8];

    const float v = a[(size_t)row * DMODEL + t] + b[(size_t)row * DMODEL + t];

    float s = v;
#pragma unroll
    for (int o = 16; o > 0; o >>= 1) s += __shfl_xor_sync(0xffffffffu, s, o);
    if (lane == 0) red[warp] = s;
    __syncthreads();
    if (warp == 0) {
        float x = (lane < 8) ? red[lane] : 0.f;
#pragma unroll
        for (int o = 4; o > 0; o >>= 1) x += __shfl_xor_sync(0xffffffffu, x, o);
        if (lane == 0) red[0] = x;
    }
    __syncthreads();
    const float mean = red[0] * (1.f / DMODEL);
    __syncthreads();

    const float d = v - mean;
    float s2 = d * d;
#pragma unroll
    for (int o = 16; o > 0; o >>= 1) s2 += __shfl_xor_sync(0xffffffffu, s2, o);
    if (lane == 0) red[warp] = s2;
    __syncthreads();
    if (warp == 0) {
        float x = (lane < 8) ? red[lane] : 0.f;
#pragma unroll
        for (int o = 4; o > 0; o >>= 1) x += __shfl_xor_sync(0xffffffffu, x, o);
        if (lane == 0) red[0] = x;
    }
    __syncthreads();
    const float var = red[0] * (1.f / DMODEL);

    const float r = d * rsqrtf(var + 1e-5f) * g[t] + beta[t];
    out[(size_t)row * DMODEL + t] = r;
    if (WB) {
        __nv_bfloat16 hi = __float2bfloat16(r);
        oh[(size_t)row * DMODEL + t] = hi;
        ol[(size_t)row * DMODEL + t] = __float2bfloat16(r - __bfloat162float(hi));
    }
}

// ---------------- launch ----------------
extern "C" void kernel_launch(void* const* d_in, const int* in_sizes, int n_in,
                              void* d_out, int out_size) {
    const float* src    = (const float*)d_in[0];
    const float* pos    = (const float*)d_in[1];
    const float* ref    = (const float*)d_in[2];
    const float* W_off  = (const float*)d_in[5];
    const float* b_off  = (const float*)d_in[6];
    const float* W_attn = (const float*)d_in[7];
    const float* b_attn = (const float*)d_in[8];
    const float* W_val  = (const float*)d_in[9];
    const float* b_val  = (const float*)d_in[10];
    const float* W_out  = (const float*)d_in[11];
    const float* b_out  = (const float*)d_in[12];
    const float* W1     = (const float*)d_in[13];
    const float* b1     = (const float*)d_in[14];
    const float* W2     = (const float*)d_in[15];
    const float* b2     = (const float*)d_in[16];
    const float* g1     = (const float*)d_in[17];
    const float* be1    = (const float*)d_in[18];
    const float* g2     = (const float*)d_in[19];
    const float* be2    = (const float*)d_in[20];
    float* out = (float*)d_out;

    float *val, *off, *attn, *src2, *x, *y;
    cudaGetSymbolAddress((void**)&val,  g_value);
    cudaGetSymbolAddress((void**)&off,  g_off);
    cudaGetSymbolAddress((void**)&attn, g_attn);
    cudaGetSymbolAddress((void**)&src2, g_src2);
    cudaGetSymbolAddress((void**)&x,    g_x);
    cudaGetSymbolAddress((void**)&y,    g_y);
    __nv_bfloat16 *sh, *sl, *qh, *ql, *smh, *sml, *xh, *xl, *fh, *fl;
    cudaGetSymbolAddress((void**)&sh,  g_src_h); cudaGetSymbolAddress((void**)&sl,  g_src_l);
    cudaGetSymbolAddress((void**)&qh,  g_q_h);   cudaGetSymbolAddress((void**)&ql,  g_q_l);
    cudaGetSymbolAddress((void**)&smh, g_sm_h);  cudaGetSymbolAddress((void**)&sml, g_sm_l);
    cudaGetSymbolAddress((void**)&xh,  g_x_h);   cudaGetSymbolAddress((void**)&xl,  g_x_l);
    cudaGetSymbolAddress((void**)&fh,  g_f_h);   cudaGetSymbolAddress((void**)&fl,  g_f_l);
    __nv_bfloat16 *wvh, *wvl, *woh, *wol, *wah, *wal, *wuh, *wul, *w1h, *w1l, *w2h, *w2l;
    cudaGetSymbolAddress((void**)&wvh, g_wv_h); cudaGetSymbolAddress((void**)&wvl, g_wv_l);
    cudaGetSymbolAddress((void**)&woh, g_wo_h); cudaGetSymbolAddress((void**)&wol, g_wo_l);
    cudaGetSymbolAddress((void**)&wah, g_wa_h); cudaGetSymbolAddress((void**)&wal, g_wa_l);
    cudaGetSymbolAddress((void**)&wuh, g_wu_h); cudaGetSymbolAddress((void**)&wul, g_wu_l);
    cudaGetSymbolAddress((void**)&w1h, g_w1_h); cudaGetSymbolAddress((void**)&w1l, g_w1_l);
    cudaGetSymbolAddress((void**)&w2h, g_w2_h); cudaGetSymbolAddress((void**)&w2l, g_w2_l);

    const int M = M_TOT;
    const int n = M * DMODEL;
    const int mb = (M + 127) / 128;      // 316
    dim3 tb(32, 8);

    // activation splits
    split_f32<<<(n + 255) / 256, 256>>>(src, sh, sl, n);
    add2_split<<<(n + 255) / 256, 256>>>(src, pos, qh, ql, n);

    // weight transpose+split: in [K,N] -> out [N,K]
    transpose_split<<<dim3(8, 8),  tb>>>(W_val,  wvh, wvl, 256, 256);
    transpose_split<<<dim3(8, 8),  tb>>>(W_off,  woh, wol, 256, 256);
    transpose_split<<<dim3(4, 8),  tb>>>(W_attn, wah, wal, 256, 128);
    transpose_split<<<dim3(8, 8),  tb>>>(W_out,  wuh, wul, 256, 256);
    transpose_split<<<dim3(32, 8), tb>>>(W1,     w1h, w1l, 256, 1024);
    transpose_split<<<dim3(8, 32), tb>>>(W2,     w2h, w2l, 1024, 256);

    // GEMMs on the HMMA tensor pipe (mma.sync bf16, split-K' numerics)
    mma_gemm<false, true, false><<<dim3(2, mb), 256>>>(
        sh, sl, wvh, wvl, b_val, val, nullptr, nullptr, M, 256, 256);
    mma_gemm<false, true, false><<<dim3(2, mb), 256>>>(
        qh, ql, woh, wol, b_off, off, nullptr, nullptr, M, 256, 256);
    mma_gemm<false, true, false><<<dim3(1, mb), 256>>>(
        qh, ql, wah, wal, b_attn, attn, nullptr, nullptr, M, 128, 256);

    sample_kernel<<<M, 256>>>(ref);

    mma_gemm<false, true, false><<<dim3(2, mb), 256>>>(
        smh, sml, wuh, wul, b_out, src2, nullptr, nullptr, M, 256, 256);

    add_ln_kernel<true><<<M, 256>>>(src, src2, g1, be1, x, xh, xl);

    mma_gemm<true, false, true><<<dim3(8, mb), 256>>>(
        xh, xl, w1h, w1l, b1, nullptr, fh, fl, M, 1024, 256);
    mma_gemm<false, true, false><<<dim3(2, mb), 256>>>(
        fh, fl, w2h, w2l, b2, y, nullptr, nullptr, M, 256, 1024);

    add_ln_kernel<false><<<M, 256>>>(x, y, g2, be2, out, nullptr, nullptr);
}